// round 6
// baseline (speedup 1.0000x reference)
#include <cuda_runtime.h>
#include <cstdint>

// FastText embedding-bag:
//   out[b,:] = W_in[center_ids[b],:] + sum_{i: seg[i]==b} W_sub[ngram_idx[i],:]
// seg sorted -> bag ranges precomputed into g_off by a boundary kernel.
// D = 300 floats = 75 float4 per row (1200 B).
//
// R6: PERSISTENT gather kernel — grid-stride over bags with exactly
//     (SMs x resident-blocks) CTAs. Removes wave transitions and overlaps
//     each bag's serial head with the previous bag's in-flight tail.
//     Pipeline unchanged from R5: cp.async ring, 8 rows, 2 rows/group.

#define D4    75
#define CHUNK 64
#define MAXB  65536

__device__ int g_off[MAXB + 1];

// ---------------------------------------------------------------- boundary
__global__ void bounds_kernel(const int* __restrict__ seg, int total, int B)
{
    int i = blockIdx.x * blockDim.x + threadIdx.x;
    if (i >= total) return;
    int cur  = seg[i];
    int prev = (i > 0) ? seg[i - 1] : -1;
    for (int b = prev + 1; b <= cur; ++b) g_off[b] = i;
    if (i == total - 1)
        for (int b = cur + 1; b <= B; ++b) g_off[b] = total;
}

// ---------------------------------------------------------------- helpers
__device__ __forceinline__ uint32_t smem_u32(const void* p)
{
    return (uint32_t)__cvta_generic_to_shared(p);
}
__device__ __forceinline__ void cp16(uint32_t s, const void* g)
{
    asm volatile("cp.async.cg.shared.global [%0], [%1], 16;\n" :: "r"(s), "l"(g));
}
__device__ __forceinline__ void cp_commit()
{
    asm volatile("cp.async.commit_group;\n" ::: "memory");
}
__device__ __forceinline__ void cp_wait3()
{
    asm volatile("cp.async.wait_group 3;\n" ::: "memory");
}

// ---------------------------------------------------------------- gather
__global__ void __launch_bounds__(96)
ft_bag_kernel(const int* __restrict__ center,
              const int* __restrict__ ngram,
              const float4* __restrict__ Win,
              const float4* __restrict__ Wsub,
              float4* __restrict__ out,
              int B)
{
    const int t = threadIdx.x;
    const bool act = (t < D4);

    __shared__ int    s_idx[CHUNK];       // pre-scaled: ngram * D4
    __shared__ float4 ring[8 * D4];       // 4 groups x 2 rows

    const uint32_t my0   = smem_u32(ring) + (uint32_t)t * 16u;
    const uint32_t rowSz = D4 * 16u;

    for (int b = blockIdx.x; b < B; b += gridDim.x) {
        const int lo = g_off[b];
        const int hi = g_off[b + 1];

        // word vector (overlaps staging below)
        float4 acc = make_float4(0.f, 0.f, 0.f, 0.f);
        if (act) {
            const int crow = __ldg(center + b) * D4;
            acc = __ldg(Win + crow + t);
        }

        for (int base = lo; base < hi; base += CHUNK) {
            const int n = min(hi - base, CHUNK);

            __syncthreads();                       // s_idx reuse (chunks & bags)
            if (t < n) s_idx[t] = __ldg(ngram + base + t) * D4;
            __syncthreads();

            if (act) {
                // prologue: 4 groups x 2 rows (rows 0..7), uniform predicates
                #pragma unroll
                for (int g = 0; g < 4; ++g) {
                    const int k0 = 2 * g, k1 = 2 * g + 1;
                    if (k0 < n) cp16(my0 + (uint32_t)k0 * rowSz, Wsub + s_idx[k0] + t);
                    if (k1 < n) cp16(my0 + (uint32_t)k1 * rowSz, Wsub + s_idx[k1] + t);
                    cp_commit();
                }

                // steady state: consume rows (j, j+1), refill rows (j+8, j+9)
                #pragma unroll 1
                for (int j = 0; j < n; j += 2) {
                    cp_wait3();                    // group j/2 complete
                    const int s0 = (j & 7);
                    float4 v0 = ring[s0 * D4 + t];
                    float4 v1 = make_float4(0.f, 0.f, 0.f, 0.f);
                    if (j + 1 < n) v1 = ring[(s0 + 1) * D4 + t];
                    acc.x += v0.x + v1.x;
                    acc.y += v0.y + v1.y;
                    acc.z += v0.z + v1.z;
                    acc.w += v0.w + v1.w;          // FADDs order LDS before refill

                    const int k0 = j + 8, k1 = j + 9;
                    if (k0 < n) cp16(my0 + (uint32_t)s0 * rowSz,       Wsub + s_idx[k0] + t);
                    if (k1 < n) cp16(my0 + (uint32_t)(s0 + 1) * rowSz, Wsub + s_idx[k1] + t);
                    cp_commit();                   // keeps group count aligned
                }
            }
        }

        if (act) out[b * D4 + t] = acc;
    }
}

extern "C" void kernel_launch(void* const* d_in, const int* in_sizes, int n_in,
                              void* d_out, int out_size)
{
    const int*    center = (const int*)d_in[0];
    const int*    ngram  = (const int*)d_in[1];
    const int*    seg    = (const int*)d_in[2];
    const float4* Win    = (const float4*)d_in[3];
    const float4* Wsub   = (const float4*)d_in[4];
    float4*       out    = (float4*)d_out;

    const int B     = in_sizes[0];
    const int total = in_sizes[1];
    const int Bc    = (B > MAXB) ? MAXB : B;

    // persistent launch: exactly fill the chip
    int dev = 0, sms = 148, perSM = 0;
    cudaGetDevice(&dev);
    cudaDeviceGetAttribute(&sms, cudaDevAttrMultiProcessorCount, dev);
    cudaOccupancyMaxActiveBlocksPerMultiprocessor(&perSM, ft_bag_kernel, 96, 0);
    if (perSM < 1) perSM = 1;
    int blocks = sms * perSM;
    if (blocks > B) blocks = B;

    bounds_kernel<<<(total + 255) / 256, 256>>>(seg, total, Bc);
    ft_bag_kernel<<<blocks, 96>>>(center, ngram, Win, Wsub, out, B);
}

// round 7
// speedup vs baseline: 1.0666x; 1.0666x over previous
#include <cuda_runtime.h>
#include <cstdint>

// FastText embedding-bag:
//   out[b,:] = W_in[center_ids[b],:] + sum_{i: seg[i]==b} W_sub[ngram_idx[i],:]
// seg sorted -> bag ranges precomputed into g_off by a boundary kernel.
// D = 300 floats = 75 float4 per row (1200 B).
//
// R7: R5 pipeline (best: cp.async ring, 8 rows, 2 rows/group) + PDL overlap:
//     gather launches programmatically-dependent on bounds_kernel, performs
//     all g_off-independent work (wv gather) before cudaGridDependencySynchronize,
//     hiding the bounds kernel + launch ramp under real memory traffic.

#define D4    75
#define CHUNK 64
#define MAXB  65536

__device__ int g_off[MAXB + 1];

// ---------------------------------------------------------------- boundary
__global__ void bounds_kernel(const int* __restrict__ seg, int total, int B)
{
    int i = blockIdx.x * blockDim.x + threadIdx.x;
    if (i >= total) return;
    int cur  = seg[i];
    int prev = (i > 0) ? seg[i - 1] : -1;
    for (int b = prev + 1; b <= cur; ++b) g_off[b] = i;
    if (i == total - 1)
        for (int b = cur + 1; b <= B; ++b) g_off[b] = total;
}

// ---------------------------------------------------------------- helpers
__device__ __forceinline__ uint32_t smem_u32(const void* p)
{
    return (uint32_t)__cvta_generic_to_shared(p);
}
__device__ __forceinline__ void cp16(uint32_t s, const void* g)
{
    asm volatile("cp.async.cg.shared.global [%0], [%1], 16;\n" :: "r"(s), "l"(g));
}
__device__ __forceinline__ void cp_commit()
{
    asm volatile("cp.async.commit_group;\n" ::: "memory");
}
__device__ __forceinline__ void cp_wait3()
{
    asm volatile("cp.async.wait_group 3;\n" ::: "memory");
}

// ---------------------------------------------------------------- gather
__global__ void __launch_bounds__(96)
ft_bag_kernel(const int* __restrict__ center,
              const int* __restrict__ ngram,
              const float4* __restrict__ Win,
              const float4* __restrict__ Wsub,
              float4* __restrict__ out)
{
    const int b = blockIdx.x;
    const int t = threadIdx.x;
    const bool act = (t < D4);

    __shared__ int    s_idx[CHUNK];       // pre-scaled: ngram * D4
    __shared__ float4 ring[8 * D4];       // 4 groups x 2 rows

    // ---- g_off-independent work first: overlaps the bounds kernel (PDL) ----
    float4 acc = make_float4(0.f, 0.f, 0.f, 0.f);
    if (act) {
        const int crow = __ldg(center + b) * D4;
        acc = __ldg(Win + crow + t);      // 1200 B wv gather in flight
    }

#if __CUDA_ARCH__ >= 900
    cudaGridDependencySynchronize();      // bounds_kernel results now visible
#endif

    const int lo = g_off[b];
    const int hi = g_off[b + 1];

    const uint32_t my0   = smem_u32(ring) + (uint32_t)t * 16u;
    const uint32_t rowSz = D4 * 16u;

    for (int base = lo; base < hi; base += CHUNK) {
        const int n = min(hi - base, CHUNK);

        if (base != lo) __syncthreads();
        if (t < n) s_idx[t] = __ldg(ngram + base + t) * D4;
        __syncthreads();

        if (act) {
            // prologue: 4 groups x 2 rows (rows 0..7), uniform predicates
            #pragma unroll
            for (int g = 0; g < 4; ++g) {
                const int k0 = 2 * g, k1 = 2 * g + 1;
                if (k0 < n) cp16(my0 + (uint32_t)k0 * rowSz, Wsub + s_idx[k0] + t);
                if (k1 < n) cp16(my0 + (uint32_t)k1 * rowSz, Wsub + s_idx[k1] + t);
                cp_commit();
            }

            // steady state: consume rows (j, j+1), refill rows (j+8, j+9)
            #pragma unroll 1
            for (int j = 0; j < n; j += 2) {
                cp_wait3();                        // group j/2 complete
                const int s0 = (j & 7);
                float4 v0 = ring[s0 * D4 + t];
                float4 v1 = make_float4(0.f, 0.f, 0.f, 0.f);
                if (j + 1 < n) v1 = ring[(s0 + 1) * D4 + t];
                acc.x += v0.x + v1.x;
                acc.y += v0.y + v1.y;
                acc.z += v0.z + v1.z;
                acc.w += v0.w + v1.w;              // FADDs order LDS before refill

                const int k0 = j + 8, k1 = j + 9;
                if (k0 < n) cp16(my0 + (uint32_t)s0 * rowSz,       Wsub + s_idx[k0] + t);
                if (k1 < n) cp16(my0 + (uint32_t)(s0 + 1) * rowSz, Wsub + s_idx[k1] + t);
                cp_commit();                       // keeps group count aligned
            }
        }
    }

    if (act) out[b * D4 + t] = acc;
}

extern "C" void kernel_launch(void* const* d_in, const int* in_sizes, int n_in,
                              void* d_out, int out_size)
{
    const int*    center = (const int*)d_in[0];
    const int*    ngram  = (const int*)d_in[1];
    const int*    seg    = (const int*)d_in[2];
    const float4* Win    = (const float4*)d_in[3];
    const float4* Wsub   = (const float4*)d_in[4];
    float4*       out    = (float4*)d_out;

    const int B     = in_sizes[0];
    const int total = in_sizes[1];
    const int Bc    = (B > MAXB) ? MAXB : B;

    bounds_kernel<<<(total + 511) / 512, 512>>>(seg, total, Bc);

    // Gather launched with programmatic stream serialization: it may start
    // while bounds_kernel runs; cudaGridDependencySynchronize() inside the
    // kernel guards the first g_off read.
    cudaLaunchConfig_t cfg = {};
    cfg.gridDim  = dim3((unsigned)B, 1, 1);
    cfg.blockDim = dim3(96, 1, 1);
    cfg.dynamicSmemBytes = 0;
    cudaLaunchAttribute attr[1];
    attr[0].id = cudaLaunchAttributeProgrammaticStreamSerialization;
    attr[0].val.programmaticStreamSerializationAllowed = 1;
    cfg.attrs = attr;
    cfg.numAttrs = 1;
    cudaError_t e = cudaLaunchKernelEx(&cfg, ft_bag_kernel,
                                       center, ngram, Win, Wsub, out);
    if (e != cudaSuccess) {
        // fallback: plain serialized launch (still correct)
        ft_bag_kernel<<<B, 96>>>(center, ngram, Win, Wsub, out);
    }
}

// round 8
// speedup vs baseline: 1.0723x; 1.0053x over previous
#include <cuda_runtime.h>
#include <cstdint>

// FastText embedding-bag:
//   out[b,:] = W_in[center_ids[b],:] + sum_{i: seg[i]==b} W_sub[ngram_idx[i],:]
// seg sorted ascending. D = 300 floats = 75 float4 per row (1200 B).
//
// R8: single kernel. Bag range found in-kernel by warp-cooperative 32-ary
//     search (warp0: lower_bound(b), warp1: lower_bound(b+1); ~5 ballot
//     rounds instead of 19 serial bisection steps), overlapped with the wv
//     gather. Row pipeline unchanged from R5 (best): cp.async ring, 8 rows
//     deep, 2 rows per commit group.

#define D4    75
#define CHUNK 64

// ---------------------------------------------------------------- helpers
__device__ __forceinline__ uint32_t smem_u32(const void* p)
{
    return (uint32_t)__cvta_generic_to_shared(p);
}
__device__ __forceinline__ void cp16(uint32_t s, const void* g)
{
    asm volatile("cp.async.cg.shared.global [%0], [%1], 16;\n" :: "r"(s), "l"(g));
}
__device__ __forceinline__ void cp_commit()
{
    asm volatile("cp.async.commit_group;\n" ::: "memory");
}
__device__ __forceinline__ void cp_wait3()
{
    asm volatile("cp.async.wait_group 3;\n" ::: "memory");
}

// warp-cooperative lower_bound over sorted seg[0..total): first i with seg[i]>=target
__device__ __forceinline__ int warp_lower_bound(const int* __restrict__ seg,
                                                int total, int target, int lane)
{
    int lo = 0, hi = total;
    while (hi > lo) {
        const int step = (hi - lo + 31) >> 5;           // ceil(range/32)
        const int pos  = lo + lane * step;
        const bool pred = (pos < hi) && (__ldg(seg + pos) < target);
        const unsigned m = __ballot_sync(0xFFFFFFFFu, pred);
        if (m == 0u) { hi = lo; break; }                // seg[lo] >= target -> lb = lo
        const int hsb = 31 - __clz(m);                  // highest lane with seg<target
        const int nlo = lo + hsb * step + 1;
        const int nhi = lo + (hsb + 1) * step;
        hi = (nhi < hi) ? nhi : hi;
        lo = nlo;
    }
    return lo;
}

// ---------------------------------------------------------------- gather
__global__ void __launch_bounds__(96)
ft_bag_kernel(const int* __restrict__ center,
              const int* __restrict__ ngram,
              const int* __restrict__ seg,
              const float4* __restrict__ Win,
              const float4* __restrict__ Wsub,
              float4* __restrict__ out,
              int total)
{
    const int b = blockIdx.x;
    const int t = threadIdx.x;
    const int w = t >> 5;
    const int lane = t & 31;
    const bool act = (t < D4);

    __shared__ int    s_lo, s_hi;
    __shared__ int    s_idx[CHUNK];       // pre-scaled: ngram * D4
    __shared__ float4 ring[8 * D4];       // 4 groups x 2 rows

    // wv gather issued first — its DRAM latency covers the searches below
    float4 acc = make_float4(0.f, 0.f, 0.f, 0.f);
    if (act) {
        const int crow = __ldg(center + b) * D4;
        acc = __ldg(Win + crow + t);
    }

    // warp 0 -> lower_bound(b), warp 1 -> lower_bound(b+1)
    if (w < 2) {
        const int r = warp_lower_bound(seg, total, b + w, lane);
        if (lane == 0) { if (w == 0) s_lo = r; else s_hi = r; }
    }
    __syncthreads();

    const int lo = s_lo;
    const int hi = s_hi;

    const uint32_t my0   = smem_u32(ring) + (uint32_t)t * 16u;
    const uint32_t rowSz = D4 * 16u;

    for (int base = lo; base < hi; base += CHUNK) {
        const int n = min(hi - base, CHUNK);

        if (base != lo) __syncthreads();
        if (t < n) s_idx[t] = __ldg(ngram + base + t) * D4;
        __syncthreads();

        if (act) {
            // prologue: 4 groups x 2 rows (rows 0..7), uniform predicates
            #pragma unroll
            for (int g = 0; g < 4; ++g) {
                const int k0 = 2 * g, k1 = 2 * g + 1;
                if (k0 < n) cp16(my0 + (uint32_t)k0 * rowSz, Wsub + s_idx[k0] + t);
                if (k1 < n) cp16(my0 + (uint32_t)k1 * rowSz, Wsub + s_idx[k1] + t);
                cp_commit();
            }

            // steady state: consume rows (j, j+1), refill rows (j+8, j+9)
            #pragma unroll 1
            for (int j = 0; j < n; j += 2) {
                cp_wait3();                        // group j/2 complete
                const int s0 = (j & 7);
                float4 v0 = ring[s0 * D4 + t];
                float4 v1 = make_float4(0.f, 0.f, 0.f, 0.f);
                if (j + 1 < n) v1 = ring[(s0 + 1) * D4 + t];
                acc.x += v0.x + v1.x;
                acc.y += v0.y + v1.y;
                acc.z += v0.z + v1.z;
                acc.w += v0.w + v1.w;              // FADDs order LDS before refill

                const int k0 = j + 8, k1 = j + 9;
                if (k0 < n) cp16(my0 + (uint32_t)s0 * rowSz,       Wsub + s_idx[k0] + t);
                if (k1 < n) cp16(my0 + (uint32_t)(s0 + 1) * rowSz, Wsub + s_idx[k1] + t);
                cp_commit();                       // keeps group count aligned
            }
        }
    }

    if (act) out[b * D4 + t] = acc;
}

extern "C" void kernel_launch(void* const* d_in, const int* in_sizes, int n_in,
                              void* d_out, int out_size)
{
    const int*    center = (const int*)d_in[0];
    const int*    ngram  = (const int*)d_in[1];
    const int*    seg    = (const int*)d_in[2];
    const float4* Win    = (const float4*)d_in[3];
    const float4* Wsub   = (const float4*)d_in[4];
    float4*       out    = (float4*)d_out;

    const int B     = in_sizes[0];
    const int total = in_sizes[1];

    ft_bag_kernel<<<B, 96>>>(center, ngram, seg, Win, Wsub, out, total);
}